// round 8
// baseline (speedup 1.0000x reference)
#include <cuda_runtime.h>
#include <math.h>

static constexpr int N_ROWS = 8192;
static constexpr int A_ART  = 32;
static constexpr int D_DIM  = 768;
static constexpr int O_DIM  = 256;
static constexpr float LN_EPS = 1e-5f;

static constexpr int MT = 32;       // rows per CTA in projection kernel
static constexpr int KC = 16;       // k-chunk
static constexpr int NCHUNK = D_DIM / KC;   // 48

// pooled scratch (zero-init; rows with cnt==0 never written/used -> deterministic)
__device__ float g_pooled[(size_t)N_ROWS * D_DIM];

// ---------------------------------------------------------------------------
__device__ __forceinline__ bool counts_is_i64(const int* __restrict__ cw) {
    bool i64 = true;
    #pragma unroll
    for (int i = 0; i < 32; ++i)
        if (cw[2 * i + 1] != 0) i64 = false;
    return i64;
}
__device__ __forceinline__ int load_count(const int* __restrict__ cw, bool i64, int n) {
    return i64 ? cw[2 * n] : cw[n];
}
__device__ __forceinline__ unsigned smem_u32(const void* p) {
    unsigned a;
    asm("{ .reg .u64 t; cvta.to.shared.u64 t, %1; cvt.u32.u64 %0, t; }"
        : "=r"(a) : "l"(p));
    return a;
}
__device__ __forceinline__ void cp16(unsigned dst, const void* src) {
    asm volatile("cp.async.cg.shared.global [%0], [%1], 16;" :: "r"(dst), "l"(src));
}

// ---------------------------------------------------------------------------
// Kernel A: online-softmax attention pooling. ONE WARP PER ROW, streaming:
// single HBM pass over valid articles, no smem staging, next article
// prefetched while the current one is scored/accumulated.
// ---------------------------------------------------------------------------
__global__ void __launch_bounds__(256, 2) pool_kernel(
    const float* __restrict__ articles,
    const int*   __restrict__ counts_w,
    const float* __restrict__ attn_w,
    const float* __restrict__ attn_b)
{
    __shared__ float s_aw[D_DIM];
    const int tid  = threadIdx.x;
    const int lane = tid & 31;
    const int wid  = tid >> 5;

    // stage attention weights (saves 24 regs vs register-resident)
    if (tid < D_DIM / 4)
        reinterpret_cast<float4*>(s_aw)[tid] =
            reinterpret_cast<const float4*>(attn_w)[tid];
    __syncthreads();

    const bool i64 = counts_is_i64(counts_w);
    const int n = blockIdx.x * 8 + wid;
    const int cnt = load_count(counts_w, i64, n);
    if (cnt <= 0) return;                      // proj writes no_news

    const float bias = attn_b[0];
    const float4* art = reinterpret_cast<const float4*>(articles)
                        + (size_t)n * (A_ART * D_DIM / 4);
    const float4* w4 = reinterpret_cast<const float4*>(s_aw);

    float4 v[6], nv[6], acc[6];
    #pragma unroll
    for (int j = 0; j < 6; ++j) {
        v[j] = art[lane + 32 * j];
        acc[j] = make_float4(0.f, 0.f, 0.f, 0.f);
    }
    float m = -3.0e38f, s = 0.f;

    for (int a = 0;;) {
        const bool more = (a + 1 < cnt);
        if (more) {                            // prefetch next article
            const float4* nx = art + (a + 1) * (D_DIM / 4);
            #pragma unroll
            for (int j = 0; j < 6; ++j) nv[j] = nx[lane + 32 * j];
        }
        // score = dot(article, attn_w) + b
        float part = 0.f;
        #pragma unroll
        for (int j = 0; j < 6; ++j) {
            const float4 w = w4[lane + 32 * j];
            part += v[j].x * w.x + v[j].y * w.y + v[j].z * w.z + v[j].w * w.w;
        }
        #pragma unroll
        for (int o = 16; o > 0; o >>= 1)
            part += __shfl_xor_sync(0xffffffffu, part, o);
        const float score = part + bias;

        // online softmax update
        const float mn = fmaxf(m, score);
        const float c  = expf(m - mn);         // 0 on first iter (m = -inf)
        const float e  = expf(score - mn);
        #pragma unroll
        for (int j = 0; j < 6; ++j) {
            acc[j].x = fmaf(e, v[j].x, acc[j].x * c);
            acc[j].y = fmaf(e, v[j].y, acc[j].y * c);
            acc[j].z = fmaf(e, v[j].z, acc[j].z * c);
            acc[j].w = fmaf(e, v[j].w, acc[j].w * c);
        }
        s = s * c + e;
        m = mn;
        ++a;
        if (!more) break;
        #pragma unroll
        for (int j = 0; j < 6; ++j) v[j] = nv[j];
    }

    const float inv = 1.0f / s;
    float4* outp = reinterpret_cast<float4*>(g_pooled) + (size_t)n * (D_DIM / 4);
    #pragma unroll
    for (int j = 0; j < 6; ++j)
        outp[lane + 32 * j] = make_float4(acc[j].x * inv, acc[j].y * inv,
                                          acc[j].z * inv, acc[j].w * inv);
}

// ---------------------------------------------------------------------------
// Kernel B: [8192,768]@[768,256] + bias + LN + exact GELU + no_news.
// 32-row tiles, 128 threads (8x8 per thread), FFMA2 inner loop, and a
// 2-stage cp.async pipeline so weight/pooled chunk loads are never exposed.
// ---------------------------------------------------------------------------
__device__ __forceinline__ unsigned long long pack2(float lo, float hi) {
    unsigned long long r;
    asm("mov.b64 %0, {%1, %2};" : "=l"(r) : "f"(lo), "f"(hi));
    return r;
}
__device__ __forceinline__ void ffma2(unsigned long long& d,
                                      unsigned long long a,
                                      unsigned long long b) {
    asm("fma.rn.f32x2 %0, %1, %2, %0;" : "+l"(d) : "l"(a), "l"(b));
}
__device__ __forceinline__ float2 unpack2(unsigned long long v) {
    float lo, hi;
    asm("mov.b64 {%0, %1}, %2;" : "=f"(lo), "=f"(hi) : "l"(v));
    return make_float2(lo, hi);
}

static constexpr int WBUF_F = KC * O_DIM;        // 4096 floats
static constexpr int PBUF_F = MT * KC;           // 512 floats
static constexpr int BUF_F  = WBUF_F + PBUF_F;   // 4608 floats per stage

__device__ __forceinline__ void stage_chunk(
    int k0, float* wbuf, float* pbuf,
    const float* __restrict__ proj_w, const float* pooled_base, int tid)
{
    const unsigned wb = smem_u32(wbuf);
    #pragma unroll
    for (int j = 0; j < 8; ++j) {                // 1024 x 16B, 8 per thread
        const int idx = tid + 128 * j;
        cp16(wb + idx * 16, proj_w + (size_t)k0 * O_DIM + idx * 4);
    }
    const unsigned pb = smem_u32(pbuf);          // 32 rows x 16 k, 1 per thread
    const int r = tid >> 2, q = tid & 3;
    cp16(pb + tid * 16, pooled_base + (size_t)r * D_DIM + k0 + q * 4);
}

__global__ void __launch_bounds__(128, 3) proj_kernel(
    const int*   __restrict__ counts_w,
    const float* __restrict__ proj_w,     // [768][256] row-major
    const float* __restrict__ proj_b,
    const float* __restrict__ ln_w,
    const float* __restrict__ ln_b,
    const float* __restrict__ no_news,
    float*       __restrict__ out)
{
    extern __shared__ float dynB[];              // 2 stages x (w + p)

    const bool i64 = counts_is_i64(counts_w);
    const int tid  = threadIdx.x;
    const int row0 = blockIdx.x * MT;
    const int cg = tid & 31;                     // cols c0..c0+7 (lane)
    const int rg = tid >> 5;                     // rows r0..r0+7 (warp)
    const int c0 = cg * 8;
    const int r0 = rg * 8;

    unsigned long long acc[8][4];
    #pragma unroll
    for (int i = 0; i < 8; ++i)
        #pragma unroll
        for (int j = 0; j < 4; ++j) acc[i][j] = 0ull;

    const float* pooled_base = g_pooled + (size_t)row0 * D_DIM;

    // pipeline prologue: chunks 0 and 1 in flight
    stage_chunk(0, dynB, dynB + WBUF_F, proj_w, pooled_base, tid);
    asm volatile("cp.async.commit_group;" ::: "memory");
    stage_chunk(KC, dynB + BUF_F, dynB + BUF_F + WBUF_F, proj_w, pooled_base, tid);
    asm volatile("cp.async.commit_group;" ::: "memory");

    #pragma unroll 1
    for (int c = 0; c < NCHUNK; ++c) {
        asm volatile("cp.async.wait_group 1;" ::: "memory");
        __syncthreads();

        const float* w_s = dynB + (c & 1) * BUF_F;
        const float* p_s = w_s + WBUF_F;

        #pragma unroll
        for (int kk = 0; kk < KC; ++kk) {
            const float* wrow = &w_s[kk * O_DIM + c0];
            const ulonglong2 w01 = *reinterpret_cast<const ulonglong2*>(wrow);
            const ulonglong2 w23 = *reinterpret_cast<const ulonglong2*>(wrow + 4);
            #pragma unroll
            for (int i = 0; i < 8; ++i) {
                const float p = p_s[(r0 + i) * KC + kk];   // broadcast LDS
                const unsigned long long pp = pack2(p, p);
                ffma2(acc[i][0], pp, w01.x);
                ffma2(acc[i][1], pp, w01.y);
                ffma2(acc[i][2], pp, w23.x);
                ffma2(acc[i][3], pp, w23.y);
            }
        }
        __syncthreads();
        if (c + 2 < NCHUNK)
            stage_chunk((c + 2) * KC, dynB + (c & 1) * BUF_F,
                        dynB + (c & 1) * BUF_F + WBUF_F,
                        proj_w, pooled_base, tid);
        asm volatile("cp.async.commit_group;" ::: "memory");
    }

    // ---- epilogue: bias + LayerNorm (register/shuffle) + exact GELU ----
    const float4 b0  = reinterpret_cast<const float4*>(proj_b)[cg * 2];
    const float4 b1  = reinterpret_cast<const float4*>(proj_b)[cg * 2 + 1];
    const float4 lw0 = reinterpret_cast<const float4*>(ln_w)[cg * 2];
    const float4 lw1 = reinterpret_cast<const float4*>(ln_w)[cg * 2 + 1];
    const float4 lb0 = reinterpret_cast<const float4*>(ln_b)[cg * 2];
    const float4 lb1 = reinterpret_cast<const float4*>(ln_b)[cg * 2 + 1];

    #pragma unroll
    for (int i = 0; i < 8; ++i) {
        const float2 v0 = unpack2(acc[i][0]);
        const float2 v1 = unpack2(acc[i][1]);
        const float2 v2 = unpack2(acc[i][2]);
        const float2 v3 = unpack2(acc[i][3]);
        float h[8];
        h[0] = v0.x + b0.x; h[1] = v0.y + b0.y;
        h[2] = v1.x + b0.z; h[3] = v1.y + b0.w;
        h[4] = v2.x + b1.x; h[5] = v2.y + b1.y;
        h[6] = v3.x + b1.z; h[7] = v3.y + b1.w;

        float ssum = 0.f;
        #pragma unroll
        for (int j = 0; j < 8; ++j) ssum += h[j];
        #pragma unroll
        for (int o = 16; o > 0; o >>= 1) ssum += __shfl_xor_sync(0xffffffffu, ssum, o);
        const float mu = ssum * (1.f / O_DIM);

        float sq = 0.f;
        #pragma unroll
        for (int j = 0; j < 8; ++j) { const float d = h[j] - mu; sq += d * d; }
        #pragma unroll
        for (int o = 16; o > 0; o >>= 1) sq += __shfl_xor_sync(0xffffffffu, sq, o);
        const float inv = rsqrtf(sq * (1.f / O_DIM) + LN_EPS);

        const int n   = row0 + r0 + i;
        const int cnt = load_count(counts_w, i64, n);

        float res[8];
        if (cnt > 0) {
            const float lw[8] = {lw0.x, lw0.y, lw0.z, lw0.w, lw1.x, lw1.y, lw1.z, lw1.w};
            const float lb[8] = {lb0.x, lb0.y, lb0.z, lb0.w, lb1.x, lb1.y, lb1.z, lb1.w};
            #pragma unroll
            for (int j = 0; j < 8; ++j) {
                const float x = (h[j] - mu) * inv * lw[j] + lb[j];
                res[j] = 0.5f * x * (1.f + erff(x * 0.70710678118654752f));
            }
        } else {
            const float4 nn0 = reinterpret_cast<const float4*>(no_news)[cg * 2];
            const float4 nn1 = reinterpret_cast<const float4*>(no_news)[cg * 2 + 1];
            res[0] = nn0.x; res[1] = nn0.y; res[2] = nn0.z; res[3] = nn0.w;
            res[4] = nn1.x; res[5] = nn1.y; res[6] = nn1.z; res[7] = nn1.w;
        }
        float4* o4 = reinterpret_cast<float4*>(out + (size_t)n * O_DIM + c0);
        o4[0] = make_float4(res[0], res[1], res[2], res[3]);
        o4[1] = make_float4(res[4], res[5], res[6], res[7]);
    }
}

// ---------------------------------------------------------------------------
extern "C" void kernel_launch(void* const* d_in, const int* in_sizes, int n_in,
                              void* d_out, int out_size)
{
    const float* articles = (const float*)d_in[0];
    const int*   counts_w = (const int*)d_in[1];
    const float* attn_w   = (const float*)d_in[2];
    const float* attn_b   = (const float*)d_in[3];
    const float* proj_w   = (const float*)d_in[4];
    const float* proj_b   = (const float*)d_in[5];
    const float* ln_w     = (const float*)d_in[6];
    const float* ln_b     = (const float*)d_in[7];
    const float* no_news  = (const float*)d_in[8];
    float* out = (float*)d_out;

    const int smemB = 2 * BUF_F * (int)sizeof(float);   // 36864 B
    cudaFuncSetAttribute(proj_kernel, cudaFuncAttributeMaxDynamicSharedMemorySize, smemB);

    pool_kernel<<<N_ROWS / 8, 256>>>(articles, counts_w, attn_w, attn_b);
    proj_kernel<<<N_ROWS / MT, 128, smemB>>>(counts_w, proj_w, proj_b,
                                             ln_w, ln_b, no_news, out);
}

// round 11
// speedup vs baseline: 1.6388x; 1.6388x over previous
#include <cuda_runtime.h>
#include <cuda_bf16.h>
#include <math.h>

static constexpr int N_ROWS = 8192;
static constexpr int A_ART  = 32;
static constexpr int D_DIM  = 768;
static constexpr int O_DIM  = 256;
static constexpr float LN_EPS = 1e-5f;

// ---------------- GEMM geometry --------------------------------------------
static constexpr int CTA_M = 64;                    // rows per CTA
static constexpr int G_TILES = N_ROWS / CTA_M;      // 128 CTAs
static constexpr int KCH = 32;                      // k per chunk
static constexpr int NCH = D_DIM / KCH;             // 24 chunks
static constexpr int PITCH = 40;                    // bf16 per smem row (20 words)
static constexpr int A_SZ = CTA_M * PITCH * 2;      // 5120 B  per split
static constexpr int B_SZ = O_DIM * PITCH * 2;      // 20480 B per split
static constexpr int OFF_AH = 0;
static constexpr int OFF_AL = A_SZ;                 // 5120
static constexpr int OFF_BH = 2 * A_SZ;             // 10240
static constexpr int OFF_BL = 2 * A_SZ + B_SZ;      // 30720
static constexpr int STAGE  = 2 * (A_SZ + B_SZ);    // 51200
static constexpr int HPITCH = 260;                  // f32 epilogue tile pitch

// bf16 hi/lo operand planes (zero-init; cnt==0 rows never written -> bias-only h, masked)
__device__ unsigned short g_Ah[(size_t)N_ROWS * D_DIM];
__device__ unsigned short g_Al[(size_t)N_ROWS * D_DIM];
__device__ unsigned short g_Bh[(size_t)O_DIM * D_DIM];   // [n][k]
__device__ unsigned short g_Bl[(size_t)O_DIM * D_DIM];

// ---------------------------------------------------------------------------
__device__ __forceinline__ bool counts_is_i64(const int* __restrict__ cw) {
    bool i64 = true;
    #pragma unroll
    for (int i = 0; i < 32; ++i)
        if (cw[2 * i + 1] != 0) i64 = false;
    return i64;
}
__device__ __forceinline__ int load_count(const int* __restrict__ cw, bool i64, int n) {
    return i64 ? cw[2 * n] : cw[n];
}
__device__ __forceinline__ unsigned smem_u32(const void* p) {
    unsigned a;
    asm("{ .reg .u64 t; cvta.to.shared.u64 t, %1; cvt.u32.u64 %0, t; }"
        : "=r"(a) : "l"(p));
    return a;
}
__device__ __forceinline__ void cp16(unsigned dst, const void* src) {
    asm volatile("cp.async.cg.shared.global [%0], [%1], 16;" :: "r"(dst), "l"(src));
}
__device__ __forceinline__ void bf16_split(float x, unsigned short& h, unsigned short& l) {
    const __nv_bfloat16 hb = __float2bfloat16(x);
    h = __bfloat16_as_ushort(hb);
    l = __bfloat16_as_ushort(__float2bfloat16(x - __bfloat162float(hb)));
}

// ---------------------------------------------------------------------------
// Weight prep: proj_w [768][256] f32 -> Bh/Bl [256][768] bf16 (coalesced both sides)
// ---------------------------------------------------------------------------
__global__ void prep_w_kernel(const float* __restrict__ proj_w) {
    __shared__ float t[32][257];
    const int tid = threadIdx.x;
    const int k0 = blockIdx.x * 32;
    #pragma unroll
    for (int j = 0; j < 32; ++j)
        t[j][tid] = proj_w[(size_t)(k0 + j) * O_DIM + tid];
    __syncthreads();
    unsigned short hs[32], ls[32];
    #pragma unroll
    for (int j = 0; j < 32; ++j)
        bf16_split(t[j][tid], hs[j], ls[j]);
    uint4* dh = reinterpret_cast<uint4*>(&g_Bh[(size_t)tid * D_DIM + k0]);
    uint4* dl = reinterpret_cast<uint4*>(&g_Bl[(size_t)tid * D_DIM + k0]);
    #pragma unroll
    for (int q = 0; q < 4; ++q) {
        const unsigned short* h8 = hs + q * 8;
        const unsigned short* l8 = ls + q * 8;
        dh[q] = make_uint4(h8[0]|(h8[1]<<16), h8[2]|(h8[3]<<16),
                           h8[4]|(h8[5]<<16), h8[6]|(h8[7]<<16));
        dl[q] = make_uint4(l8[0]|(l8[1]<<16), l8[2]|(l8[3]<<16),
                           l8[4]|(l8[5]<<16), l8[6]|(l8[7]<<16));
    }
}

// ---------------------------------------------------------------------------
// Kernel A: masked attention softmax pooling (proven R5 staging variant).
// Epilogue emits pooled row as bf16 hi/lo planes.
// ---------------------------------------------------------------------------
__global__ void __launch_bounds__(256, 2) pool_kernel(
    const float* __restrict__ articles,
    const int*   __restrict__ counts_w,
    const float* __restrict__ attn_w,
    const float* __restrict__ attn_b)
{
    extern __shared__ float s_art[];          // [32][768]
    __shared__ float s_aw[D_DIM];
    __shared__ float s_scores[A_ART];
    __shared__ float s_wt[A_ART];

    const bool i64 = counts_is_i64(counts_w);
    const int n = blockIdx.x;
    const int cnt = load_count(counts_w, i64, n);
    if (cnt <= 0) return;                     // gemm epilogue writes no_news

    const int tid  = threadIdx.x;
    const int wid  = tid >> 5;
    const int lane = tid & 31;

    const float* src = articles + (size_t)n * A_ART * D_DIM;
    const unsigned sbase = smem_u32(s_art);
    const int nf4 = cnt * (D_DIM / 4);
    for (int idx = tid; idx < nf4; idx += 256)
        cp16(sbase + idx * 16, src + idx * 4);
    asm volatile("cp.async.commit_group;" ::: "memory");

    if (tid < D_DIM / 4)
        reinterpret_cast<float4*>(s_aw)[tid] =
            reinterpret_cast<const float4*>(attn_w)[tid];

    asm volatile("cp.async.wait_group 0;" ::: "memory");
    __syncthreads();

    for (int a = wid; a < cnt; a += 8) {
        const float4* v4 = reinterpret_cast<const float4*>(s_art + a * D_DIM);
        const float4* w4 = reinterpret_cast<const float4*>(s_aw);
        float part = 0.f;
        #pragma unroll
        for (int j = 0; j < 6; ++j) {
            const int idx = lane + 32 * j;
            const float4 v = v4[idx];
            const float4 w = w4[idx];
            part += v.x * w.x + v.y * w.y + v.z * w.z + v.w * w.w;
        }
        #pragma unroll
        for (int o = 16; o > 0; o >>= 1)
            part += __shfl_xor_sync(0xffffffffu, part, o);
        if (lane == 0) s_scores[a] = part;
    }
    __syncthreads();

    if (wid == 0) {
        const float b = attn_b[0];
        float s = (lane < cnt) ? (s_scores[lane] + b) : -3.0e38f;
        float m = s;
        #pragma unroll
        for (int o = 16; o > 0; o >>= 1)
            m = fmaxf(m, __shfl_xor_sync(0xffffffffu, m, o));
        float e = (lane < cnt) ? expf(s - m) : 0.f;
        float sum = e;
        #pragma unroll
        for (int o = 16; o > 0; o >>= 1)
            sum += __shfl_xor_sync(0xffffffffu, sum, o);
        if (lane < cnt) s_wt[lane] = e / sum;
    }
    __syncthreads();

    if (tid < D_DIM / 4) {
        float4 acc = make_float4(0.f, 0.f, 0.f, 0.f);
        for (int a = 0; a < cnt; ++a) {
            const float wa = s_wt[a];
            const float4 v = reinterpret_cast<const float4*>(s_art + a * D_DIM)[tid];
            acc.x = fmaf(wa, v.x, acc.x);
            acc.y = fmaf(wa, v.y, acc.y);
            acc.z = fmaf(wa, v.z, acc.z);
            acc.w = fmaf(wa, v.w, acc.w);
        }
        unsigned short hs[4], ls[4];
        bf16_split(acc.x, hs[0], ls[0]);
        bf16_split(acc.y, hs[1], ls[1]);
        bf16_split(acc.z, hs[2], ls[2]);
        bf16_split(acc.w, hs[3], ls[3]);
        const size_t base = (size_t)n * D_DIM + tid * 4;
        *reinterpret_cast<uint2*>(&g_Ah[base]) =
            make_uint2(hs[0]|(hs[1]<<16), hs[2]|(hs[3]<<16));
        *reinterpret_cast<uint2*>(&g_Al[base]) =
            make_uint2(ls[0]|(ls[1]<<16), ls[2]|(ls[3]<<16));
    }
}

// ---------------------------------------------------------------------------
// Kernel B: bf16x3 GEMM via mma.sync.m16n8k16 + bias + LN + GELU + no_news.
// ---------------------------------------------------------------------------
__device__ __forceinline__ void mma16816(float* c, const unsigned* a,
                                         unsigned b0, unsigned b1) {
    asm volatile(
        "mma.sync.aligned.m16n8k16.row.col.f32.bf16.bf16.f32 "
        "{%0,%1,%2,%3}, {%4,%5,%6,%7}, {%8,%9}, {%0,%1,%2,%3};"
        : "+f"(c[0]), "+f"(c[1]), "+f"(c[2]), "+f"(c[3])
        : "r"(a[0]), "r"(a[1]), "r"(a[2]), "r"(a[3]), "r"(b0), "r"(b1));
}

__device__ __forceinline__ void g_stage(int c, unsigned buf, int row0, int tid) {
    const int k0 = c * KCH;
    #pragma unroll
    for (int j = 0; j < 2; ++j) {                // A: 512 x 16B
        const int idx = tid + 256 * j;
        const int half = idx >> 8;
        const int row = (idx & 255) >> 2, seg = idx & 3;
        const unsigned short* src = (half ? g_Al : g_Ah)
            + (size_t)(row0 + row) * D_DIM + k0 + seg * 8;
        cp16(buf + (half ? OFF_AL : OFF_AH) + row * (PITCH*2) + seg * 16, src);
    }
    #pragma unroll
    for (int j = 0; j < 8; ++j) {                // B: 2048 x 16B
        const int idx = tid + 256 * j;
        const int half = idx >> 10;
        const int nn = (idx & 1023) >> 2, seg = idx & 3;
        const unsigned short* src = (half ? g_Bl : g_Bh)
            + (size_t)nn * D_DIM + k0 + seg * 8;
        cp16(buf + (half ? OFF_BL : OFF_BH) + nn * (PITCH*2) + seg * 16, src);
    }
}

__global__ void __launch_bounds__(256) gemm_kernel(
    const int*   __restrict__ counts_w,
    const float* __restrict__ proj_b,
    const float* __restrict__ ln_w,
    const float* __restrict__ ln_b,
    const float* __restrict__ no_news,
    float*       __restrict__ out)
{
    extern __shared__ char sm[];                 // 2 x STAGE; epilogue reuses as h
    __shared__ float s_pb[O_DIM], s_lw[O_DIM], s_lb[O_DIM], s_nn[O_DIM];

    const int tid  = threadIdx.x;
    const int wid  = tid >> 5;
    const int lane = tid & 31;
    const int row0 = blockIdx.x * CTA_M;
    const bool i64 = counts_is_i64(counts_w);

    s_pb[tid] = proj_b[tid];
    s_lw[tid] = ln_w[tid];
    s_lb[tid] = ln_b[tid];
    s_nn[tid] = no_news[tid];

    const int warp_m = wid & 1;                  // 2 x 32 rows
    const int warp_n = wid >> 1;                 // 4 x 64 cols
    const int lq = lane & 3;                     // k-pair selector
    const int lr = lane >> 2;                    // row/col within 8

    float acc[2][8][4];
    #pragma unroll
    for (int mt = 0; mt < 2; ++mt)
        #pragma unroll
        for (int nt = 0; nt < 8; ++nt)
            #pragma unroll
            for (int j = 0; j < 4; ++j) acc[mt][nt][j] = 0.f;

    const unsigned smbase = smem_u32(sm);

    g_stage(0, smbase, row0, tid);
    asm volatile("cp.async.commit_group;" ::: "memory");
    g_stage(1, smbase + STAGE, row0, tid);
    asm volatile("cp.async.commit_group;" ::: "memory");

    #pragma unroll 1
    for (int c = 0; c < NCH; ++c) {
        asm volatile("cp.async.wait_group 1;" ::: "memory");
        __syncthreads();

        const char* buf = sm + (c & 1) * STAGE;
        const unsigned* Ahw = reinterpret_cast<const unsigned*>(buf + OFF_AH);
        const unsigned* Alw = reinterpret_cast<const unsigned*>(buf + OFF_AL);
        const unsigned* Bhw = reinterpret_cast<const unsigned*>(buf + OFF_BH);
        const unsigned* Blw = reinterpret_cast<const unsigned*>(buf + OFF_BL);

        #pragma unroll
        for (int ks = 0; ks < 2; ++ks) {
            unsigned ah[2][4], al[2][4];
            #pragma unroll
            for (int mt = 0; mt < 2; ++mt) {
                const int w0 = (warp_m * 32 + mt * 16 + lr) * 20 + ks * 8 + lq;
                ah[mt][0] = Ahw[w0];       ah[mt][1] = Ahw[w0 + 160];
                ah[mt][2] = Ahw[w0 + 4];   ah[mt][3] = Ahw[w0 + 164];
                al[mt][0] = Alw[w0];       al[mt][1] = Alw[w0 + 160];
                al[mt][2] = Alw[w0 + 4];   al[mt][3] = Alw[w0 + 164];
            }
            #pragma unroll
            for (int nt = 0; nt < 8; ++nt) {
                const int wb = (warp_n * 64 + nt * 8 + lr) * 20 + ks * 8 + lq;
                const unsigned bh0 = Bhw[wb], bh1 = Bhw[wb + 4];
                const unsigned bl0 = Blw[wb], bl1 = Blw[wb + 4];
                #pragma unroll
                for (int mt = 0; mt < 2; ++mt) {
                    mma16816(acc[mt][nt], ah[mt], bh0, bh1);
                    mma16816(acc[mt][nt], ah[mt], bl0, bl1);
                    mma16816(acc[mt][nt], al[mt], bh0, bh1);
                }
            }
        }
        __syncthreads();
        if (c + 2 < NCH) g_stage(c + 2, smbase + (c & 1) * STAGE, row0, tid);
        asm volatile("cp.async.commit_group;" ::: "memory");
    }

    // ---- park h tile (+bias) in smem, then LN + GELU + no_news ----
    __syncthreads();
    float* h = reinterpret_cast<float*>(sm);     // [64][HPITCH]
    #pragma unroll
    for (int mt = 0; mt < 2; ++mt) {
        const int r = warp_m * 32 + mt * 16 + lr;
        #pragma unroll
        for (int nt = 0; nt < 8; ++nt) {
            const int cb = warp_n * 64 + nt * 8 + lq * 2;
            h[r * HPITCH + cb]           = acc[mt][nt][0] + s_pb[cb];
            h[r * HPITCH + cb + 1]       = acc[mt][nt][1] + s_pb[cb + 1];
            h[(r + 8) * HPITCH + cb]     = acc[mt][nt][2] + s_pb[cb];
            h[(r + 8) * HPITCH + cb + 1] = acc[mt][nt][3] + s_pb[cb + 1];
        }
    }
    __syncthreads();

    #pragma unroll 1
    for (int i = 0; i < 8; ++i) {
        const int r = wid * 8 + i;
        const int n_row = row0 + r;
        const float4 x0 = *reinterpret_cast<const float4*>(&h[r * HPITCH + lane * 8]);
        const float4 x1 = *reinterpret_cast<const float4*>(&h[r * HPITCH + lane * 8 + 4]);
        float v[8] = {x0.x, x0.y, x0.z, x0.w, x1.x, x1.y, x1.z, x1.w};

        float s = 0.f;
        #pragma unroll
        for (int j = 0; j < 8; ++j) s += v[j];
        #pragma unroll
        for (int o = 16; o > 0; o >>= 1) s += __shfl_xor_sync(0xffffffffu, s, o);
        const float mu = s * (1.f / O_DIM);

        float sq = 0.f;
        #pragma unroll
        for (int j = 0; j < 8; ++j) { const float d = v[j] - mu; sq += d * d; }
        #pragma unroll
        for (int o = 16; o > 0; o >>= 1) sq += __shfl_xor_sync(0xffffffffu, sq, o);
        const float inv = rsqrtf(sq * (1.f / O_DIM) + LN_EPS);

        const int cnt = load_count(counts_w, i64, n_row);
        float res[8];
        if (cnt > 0) {
            #pragma unroll
            for (int j = 0; j < 8; ++j) {
                const int col = lane * 8 + j;
                const float x = (v[j] - mu) * inv * s_lw[col] + s_lb[col];
                res[j] = 0.5f * x * (1.f + erff(x * 0.70710678118654752f));
            }
        } else {
            #pragma unroll
            for (int j = 0; j < 8; ++j) res[j] = s_nn[lane * 8 + j];
        }
        float4* o4 = reinterpret_cast<float4*>(out + (size_t)n_row * O_DIM + lane * 8);
        o4[0] = make_float4(res[0], res[1], res[2], res[3]);
        o4[1] = make_float4(res[4], res[5], res[6], res[7]);
    }
}

// ---------------------------------------------------------------------------
extern "C" void kernel_launch(void* const* d_in, const int* in_sizes, int n_in,
                              void* d_out, int out_size)
{
    const float* articles = (const float*)d_in[0];
    const int*   counts_w = (const int*)d_in[1];
    const float* attn_w   = (const float*)d_in[2];
    const float* attn_b   = (const float*)d_in[3];
    const float* proj_w   = (const float*)d_in[4];
    const float* proj_b   = (const float*)d_in[5];
    const float* ln_w     = (const float*)d_in[6];
    const float* ln_b     = (const float*)d_in[7];
    const float* no_news  = (const float*)d_in[8];
    float* out = (float*)d_out;

    const int smemA = A_ART * D_DIM * (int)sizeof(float);   // 98304 B
    const int smemG = 2 * STAGE;                            // 102400 B
    cudaFuncSetAttribute(pool_kernel, cudaFuncAttributeMaxDynamicSharedMemorySize, smemA);
    cudaFuncSetAttribute(gemm_kernel, cudaFuncAttributeMaxDynamicSharedMemorySize, smemG);

    prep_w_kernel<<<D_DIM / 32, O_DIM>>>(proj_w);
    pool_kernel<<<N_ROWS, 256, smemA>>>(articles, counts_w, attn_w, attn_b);
    gemm_kernel<<<G_TILES, 256, smemG>>>(counts_w, proj_b, ln_w, ln_b, no_news, out);
}

// round 12
// speedup vs baseline: 1.7722x; 1.0814x over previous
#include <cuda_runtime.h>
#include <cuda_bf16.h>
#include <math.h>

static constexpr int N_ROWS = 8192;
static constexpr int A_ART  = 32;
static constexpr int D_DIM  = 768;
static constexpr int O_DIM  = 256;
static constexpr float LN_EPS = 1e-5f;

// ---------------- GEMM geometry --------------------------------------------
static constexpr int CTA_M = 64;                    // rows per CTA
static constexpr int G_TILES = N_ROWS / CTA_M;      // 128 CTAs
static constexpr int KCH = 32;                      // k per chunk
static constexpr int NCH = D_DIM / KCH;             // 24 chunks
static constexpr int PITCH = 40;                    // bf16 per smem row (20 words)
static constexpr int A_SZ = CTA_M * PITCH * 2;      // 5120 B  per split
static constexpr int B_SZ = O_DIM * PITCH * 2;      // 20480 B per split
static constexpr int OFF_AH = 0;
static constexpr int OFF_AL = A_SZ;                 // 5120
static constexpr int OFF_BH = 2 * A_SZ;             // 10240
static constexpr int OFF_BL = 2 * A_SZ + B_SZ;      // 30720
static constexpr int STAGE  = 2 * (A_SZ + B_SZ);    // 51200
static constexpr int HPITCH = 260;                  // f32 epilogue tile pitch

static constexpr int NST = 24;                      // staged articles in pool

// bf16 hi/lo operand planes (zero-init; cnt==0 rows never written -> bias-only h, masked)
__device__ unsigned short g_Ah[(size_t)N_ROWS * D_DIM];
__device__ unsigned short g_Al[(size_t)N_ROWS * D_DIM];
__device__ unsigned short g_Bh[(size_t)O_DIM * D_DIM];   // [n][k]
__device__ unsigned short g_Bl[(size_t)O_DIM * D_DIM];

// ---------------------------------------------------------------------------
__device__ __forceinline__ bool counts_is_i64(const int* __restrict__ cw) {
    bool i64 = true;
    #pragma unroll
    for (int i = 0; i < 32; ++i)
        if (cw[2 * i + 1] != 0) i64 = false;
    return i64;
}
__device__ __forceinline__ int load_count(const int* __restrict__ cw, bool i64, int n) {
    return i64 ? cw[2 * n] : cw[n];
}
__device__ __forceinline__ unsigned smem_u32(const void* p) {
    unsigned a;
    asm("{ .reg .u64 t; cvta.to.shared.u64 t, %1; cvt.u32.u64 %0, t; }"
        : "=r"(a) : "l"(p));
    return a;
}
__device__ __forceinline__ void cp16(unsigned dst, const void* src) {
    asm volatile("cp.async.cg.shared.global [%0], [%1], 16;" :: "r"(dst), "l"(src));
}
__device__ __forceinline__ void bf16_split(float x, unsigned short& h, unsigned short& l) {
    const __nv_bfloat16 hb = __float2bfloat16(x);
    h = __bfloat16_as_ushort(hb);
    l = __bfloat16_as_ushort(__float2bfloat16(x - __bfloat162float(hb)));
}

// ---------------------------------------------------------------------------
// Weight prep: tiled 32x32 transpose, grid (24, 8). Coalesced loads; writes
// in 64B warp segments along k. Conflict-free smem (pitch 33).
// ---------------------------------------------------------------------------
__global__ void __launch_bounds__(256) prep_w_kernel(const float* __restrict__ proj_w) {
    __shared__ float t[32][33];
    const int k0 = blockIdx.x * 32;
    const int n0 = blockIdx.y * 32;
    const int tid = threadIdx.x;
    const int lr = tid >> 5;          // 0..7
    const int lc = tid & 31;
    #pragma unroll
    for (int j = 0; j < 4; ++j)
        t[lr + 8 * j][lc] = proj_w[(size_t)(k0 + lr + 8 * j) * O_DIM + n0 + lc];
    __syncthreads();
    const int n  = tid >> 3;          // 0..31
    const int kq = tid & 7;           // 4 k each
    unsigned short hs[4], ls[4];
    #pragma unroll
    for (int i = 0; i < 4; ++i)
        bf16_split(t[kq * 4 + i][n], hs[i], ls[i]);
    const size_t base = (size_t)(n0 + n) * D_DIM + k0 + kq * 4;
    *reinterpret_cast<uint2*>(&g_Bh[base]) =
        make_uint2(hs[0] | (hs[1] << 16), hs[2] | (hs[3] << 16));
    *reinterpret_cast<uint2*>(&g_Bl[base]) =
        make_uint2(ls[0] | (ls[1] << 16), ls[2] | (ls[3] << 16));
}

// ---------------------------------------------------------------------------
// Kernel A: masked attention softmax pooling. Stage first NST=24 articles in
// smem (73.7 KB -> 3 CTAs/SM); overflow articles (<=8, p=8/33) scored from
// GMEM and re-read (L2-hot) in the pool phase. attn_w via __ldg (L1).
// ---------------------------------------------------------------------------
__global__ void __launch_bounds__(256, 3) pool_kernel(
    const float* __restrict__ articles,
    const int*   __restrict__ counts_w,
    const float* __restrict__ attn_w,
    const float* __restrict__ attn_b)
{
    extern __shared__ float s_art[];          // [NST][768]
    __shared__ float s_scores[A_ART];
    __shared__ float s_wt[A_ART];

    const bool i64 = counts_is_i64(counts_w);
    const int n = blockIdx.x;
    const int cnt = load_count(counts_w, i64, n);
    if (cnt <= 0) return;                     // gemm epilogue writes no_news

    const int tid  = threadIdx.x;
    const int wid  = tid >> 5;
    const int lane = tid & 31;
    const int nst = cnt < NST ? cnt : NST;

    const float* src = articles + (size_t)n * A_ART * D_DIM;
    const unsigned sbase = smem_u32(s_art);
    const int nf4 = nst * (D_DIM / 4);
    for (int idx = tid; idx < nf4; idx += 256)
        cp16(sbase + idx * 16, src + idx * 4);
    asm volatile("cp.async.commit_group;" ::: "memory");
    asm volatile("cp.async.wait_group 0;" ::: "memory");
    __syncthreads();

    const float4* aw4 = reinterpret_cast<const float4*>(attn_w);
    const float4* src4 = reinterpret_cast<const float4*>(src);

    // scores: warp per article; staged from smem, overflow from gmem
    for (int a = wid; a < cnt; a += 8) {
        const float4* v4 = (a < NST)
            ? reinterpret_cast<const float4*>(s_art + a * D_DIM)
            : (src4 + a * (D_DIM / 4));
        float part = 0.f;
        #pragma unroll
        for (int j = 0; j < 6; ++j) {
            const int idx = lane + 32 * j;
            const float4 v = v4[idx];
            const float4 w = __ldg(aw4 + idx);
            part += v.x * w.x + v.y * w.y + v.z * w.z + v.w * w.w;
        }
        #pragma unroll
        for (int o = 16; o > 0; o >>= 1)
            part += __shfl_xor_sync(0xffffffffu, part, o);
        if (lane == 0) s_scores[a] = part;
    }
    __syncthreads();

    if (wid == 0) {
        const float b = attn_b[0];
        float s = (lane < cnt) ? (s_scores[lane] + b) : -3.0e38f;
        float m = s;
        #pragma unroll
        for (int o = 16; o > 0; o >>= 1)
            m = fmaxf(m, __shfl_xor_sync(0xffffffffu, m, o));
        float e = (lane < cnt) ? expf(s - m) : 0.f;
        float sum = e;
        #pragma unroll
        for (int o = 16; o > 0; o >>= 1)
            sum += __shfl_xor_sync(0xffffffffu, sum, o);
        if (lane < cnt) s_wt[lane] = e / sum;
    }
    __syncthreads();

    if (tid < D_DIM / 4) {
        float4 acc = make_float4(0.f, 0.f, 0.f, 0.f);
        for (int a = 0; a < nst; ++a) {
            const float wa = s_wt[a];
            const float4 v = reinterpret_cast<const float4*>(s_art + a * D_DIM)[tid];
            acc.x = fmaf(wa, v.x, acc.x);
            acc.y = fmaf(wa, v.y, acc.y);
            acc.z = fmaf(wa, v.z, acc.z);
            acc.w = fmaf(wa, v.w, acc.w);
        }
        for (int a = NST; a < cnt; ++a) {     // overflow: L2-hot re-read
            const float wa = s_wt[a];
            const float4 v = src4[a * (D_DIM / 4) + tid];
            acc.x = fmaf(wa, v.x, acc.x);
            acc.y = fmaf(wa, v.y, acc.y);
            acc.z = fmaf(wa, v.z, acc.z);
            acc.w = fmaf(wa, v.w, acc.w);
        }
        unsigned short hs[4], ls[4];
        bf16_split(acc.x, hs[0], ls[0]);
        bf16_split(acc.y, hs[1], ls[1]);
        bf16_split(acc.z, hs[2], ls[2]);
        bf16_split(acc.w, hs[3], ls[3]);
        const size_t base = (size_t)n * D_DIM + tid * 4;
        *reinterpret_cast<uint2*>(&g_Ah[base]) =
            make_uint2(hs[0] | (hs[1] << 16), hs[2] | (hs[3] << 16));
        *reinterpret_cast<uint2*>(&g_Al[base]) =
            make_uint2(ls[0] | (ls[1] << 16), ls[2] | (ls[3] << 16));
    }
}

// ---------------------------------------------------------------------------
// Kernel B: bf16x3 GEMM (mma.sync.m16n8k16) with ldmatrix fragment loads and
// a 3-stage cp.async pipeline (one __syncthreads per chunk).
// ---------------------------------------------------------------------------
__device__ __forceinline__ void mma16816(float* c, const unsigned* a,
                                         unsigned b0, unsigned b1) {
    asm volatile(
        "mma.sync.aligned.m16n8k16.row.col.f32.bf16.bf16.f32 "
        "{%0,%1,%2,%3}, {%4,%5,%6,%7}, {%8,%9}, {%0,%1,%2,%3};"
        : "+f"(c[0]), "+f"(c[1]), "+f"(c[2]), "+f"(c[3])
        : "r"(a[0]), "r"(a[1]), "r"(a[2]), "r"(a[3]), "r"(b0), "r"(b1));
}
__device__ __forceinline__ void ldsm4(unsigned* d, unsigned addr) {
    asm volatile("ldmatrix.sync.aligned.m8n8.x4.shared.b16 {%0,%1,%2,%3}, [%4];"
                 : "=r"(d[0]), "=r"(d[1]), "=r"(d[2]), "=r"(d[3]) : "r"(addr));
}

__device__ __forceinline__ void g_stage(int c, unsigned buf, int row0, int tid) {
    const int k0 = c * KCH;
    #pragma unroll
    for (int j = 0; j < 2; ++j) {                // A: 512 x 16B
        const int idx = tid + 256 * j;
        const int half = idx >> 8;
        const int row = (idx & 255) >> 2, seg = idx & 3;
        const unsigned short* src = (half ? g_Al : g_Ah)
            + (size_t)(row0 + row) * D_DIM + k0 + seg * 8;
        cp16(buf + (half ? OFF_AL : OFF_AH) + row * (PITCH*2) + seg * 16, src);
    }
    #pragma unroll
    for (int j = 0; j < 8; ++j) {                // B: 2048 x 16B
        const int idx = tid + 256 * j;
        const int half = idx >> 10;
        const int nn = (idx & 1023) >> 2, seg = idx & 3;
        const unsigned short* src = (half ? g_Bl : g_Bh)
            + (size_t)nn * D_DIM + k0 + seg * 8;
        cp16(buf + (half ? OFF_BL : OFF_BH) + nn * (PITCH*2) + seg * 16, src);
    }
}

__global__ void __launch_bounds__(256) gemm_kernel(
    const int*   __restrict__ counts_w,
    const float* __restrict__ proj_b,
    const float* __restrict__ ln_w,
    const float* __restrict__ ln_b,
    const float* __restrict__ no_news,
    float*       __restrict__ out)
{
    extern __shared__ char sm[];                 // 3 x STAGE; epilogue reuses as h
    __shared__ float s_pb[O_DIM], s_lw[O_DIM], s_lb[O_DIM], s_nn[O_DIM];

    const int tid  = threadIdx.x;
    const int wid  = tid >> 5;
    const int lane = tid & 31;
    const int row0 = blockIdx.x * CTA_M;
    const bool i64 = counts_is_i64(counts_w);

    s_pb[tid] = proj_b[tid];
    s_lw[tid] = ln_w[tid];
    s_lb[tid] = ln_b[tid];
    s_nn[tid] = no_news[tid];

    const int warp_m = wid & 1;                  // 2 x 32 rows
    const int warp_n = wid >> 1;                 // 4 x 64 cols
    const int lq = lane & 3;
    const int lr = lane >> 2;

    float acc[2][8][4];
    #pragma unroll
    for (int mt = 0; mt < 2; ++mt)
        #pragma unroll
        for (int nt = 0; nt < 8; ++nt)
            #pragma unroll
            for (int j = 0; j < 4; ++j) acc[mt][nt][j] = 0.f;

    const unsigned smbase = smem_u32(sm);

    // ldmatrix per-lane address components (byte offsets, pitch 80B)
    const unsigned a_lane = (unsigned)((lane & 15) * 80 + (lane >> 4) * 16);
    const unsigned b_lane = (unsigned)((((lane >> 4) & 1) * 8 + (lane & 7)) * 80
                                       + ((lane >> 3) & 1) * 16);
    unsigned aoffH[2], aoffL[2];
    #pragma unroll
    for (int mt = 0; mt < 2; ++mt) {
        const unsigned r = (unsigned)((warp_m * 32 + mt * 16) * 80) + a_lane;
        aoffH[mt] = OFF_AH + r;
        aoffL[mt] = OFF_AL + r;
    }
    unsigned boffH[4], boffL[4];
    #pragma unroll
    for (int p = 0; p < 4; ++p) {
        const unsigned r = (unsigned)((warp_n * 64 + p * 16) * 80) + b_lane;
        boffH[p] = OFF_BH + r;
        boffL[p] = OFF_BL + r;
    }

    g_stage(0, smbase, row0, tid);
    asm volatile("cp.async.commit_group;" ::: "memory");
    g_stage(1, smbase + STAGE, row0, tid);
    asm volatile("cp.async.commit_group;" ::: "memory");

    #pragma unroll 1
    for (int c = 0; c < NCH; ++c) {
        asm volatile("cp.async.wait_group 1;" ::: "memory");
        __syncthreads();

        if (c + 2 < NCH)
            g_stage(c + 2, smbase + ((c + 2) % 3) * STAGE, row0, tid);
        asm volatile("cp.async.commit_group;" ::: "memory");

        const unsigned buf = smbase + (c % 3) * STAGE;
        #pragma unroll
        for (int ks = 0; ks < 2; ++ks) {
            const unsigned ko = ks * 32;
            unsigned ah[2][4], al[2][4];
            #pragma unroll
            for (int mt = 0; mt < 2; ++mt) {
                ldsm4(ah[mt], buf + aoffH[mt] + ko);
                ldsm4(al[mt], buf + aoffL[mt] + ko);
            }
            #pragma unroll
            for (int p = 0; p < 4; ++p) {
                unsigned bh[4], bl[4];
                ldsm4(bh, buf + boffH[p] + ko);
                ldsm4(bl, buf + boffL[p] + ko);
                #pragma unroll
                for (int s = 0; s < 2; ++s) {     // nt = 2p+s
                    const int nt = 2 * p + s;
                    const unsigned h0 = bh[2*s], h1 = bh[2*s+1];
                    const unsigned l0 = bl[2*s], l1 = bl[2*s+1];
                    #pragma unroll
                    for (int mt = 0; mt < 2; ++mt) {
                        mma16816(acc[mt][nt], ah[mt], h0, h1);
                        mma16816(acc[mt][nt], ah[mt], l0, l1);
                        mma16816(acc[mt][nt], al[mt], h0, h1);
                    }
                }
            }
        }
    }

    // ---- park h tile (+bias) in smem, then LN + GELU + no_news ----
    __syncthreads();
    float* h = reinterpret_cast<float*>(sm);     // [64][HPITCH]
    #pragma unroll
    for (int mt = 0; mt < 2; ++mt) {
        const int r = warp_m * 32 + mt * 16 + lr;
        #pragma unroll
        for (int nt = 0; nt < 8; ++nt) {
            const int cb = warp_n * 64 + nt * 8 + lq * 2;
            h[r * HPITCH + cb]           = acc[mt][nt][0] + s_pb[cb];
            h[r * HPITCH + cb + 1]       = acc[mt][nt][1] + s_pb[cb + 1];
            h[(r + 8) * HPITCH + cb]     = acc[mt][nt][2] + s_pb[cb];
            h[(r + 8) * HPITCH + cb + 1] = acc[mt][nt][3] + s_pb[cb + 1];
        }
    }
    __syncthreads();

    #pragma unroll 1
    for (int i = 0; i < 8; ++i) {
        const int r = wid * 8 + i;
        const int n_row = row0 + r;
        const float4 x0 = *reinterpret_cast<const float4*>(&h[r * HPITCH + lane * 8]);
        const float4 x1 = *reinterpret_cast<const float4*>(&h[r * HPITCH + lane * 8 + 4]);
        float v[8] = {x0.x, x0.y, x0.z, x0.w, x1.x, x1.y, x1.z, x1.w};

        float s = 0.f;
        #pragma unroll
        for (int j = 0; j < 8; ++j) s += v[j];
        #pragma unroll
        for (int o = 16; o > 0; o >>= 1) s += __shfl_xor_sync(0xffffffffu, s, o);
        const float mu = s * (1.f / O_DIM);

        float sq = 0.f;
        #pragma unroll
        for (int j = 0; j < 8; ++j) { const float d = v[j] - mu; sq += d * d; }
        #pragma unroll
        for (int o = 16; o > 0; o >>= 1) sq += __shfl_xor_sync(0xffffffffu, sq, o);
        const float inv = rsqrtf(sq * (1.f / O_DIM) + LN_EPS);

        const int cnt = load_count(counts_w, i64, n_row);
        float res[8];
        if (cnt > 0) {
            #pragma unroll
            for (int j = 0; j < 8; ++j) {
                const int col = lane * 8 + j;
                const float x = (v[j] - mu) * inv * s_lw[col] + s_lb[col];
                res[j] = 0.5f * x * (1.f + erff(x * 0.70710678118654752f));
            }
        } else {
            #pragma unroll
            for (int j = 0; j < 8; ++j) res[j] = s_nn[lane * 8 + j];
        }
        float4* o4 = reinterpret_cast<float4*>(out + (size_t)n_row * O_DIM + lane * 8);
        o4[0] = make_float4(res[0], res[1], res[2], res[3]);
        o4[1] = make_float4(res[4], res[5], res[6], res[7]);
    }
}

// ---------------------------------------------------------------------------
extern "C" void kernel_launch(void* const* d_in, const int* in_sizes, int n_in,
                              void* d_out, int out_size)
{
    const float* articles = (const float*)d_in[0];
    const int*   counts_w = (const int*)d_in[1];
    const float* attn_w   = (const float*)d_in[2];
    const float* attn_b   = (const float*)d_in[3];
    const float* proj_w   = (const float*)d_in[4];
    const float* proj_b   = (const float*)d_in[5];
    const float* ln_w     = (const float*)d_in[6];
    const float* ln_b     = (const float*)d_in[7];
    const float* no_news  = (const float*)d_in[8];
    float* out = (float*)d_out;

    const int smemA = NST * D_DIM * (int)sizeof(float);     // 73728 B -> 3 CTAs/SM
    const int smemG = 3 * STAGE;                            // 153600 B
    cudaFuncSetAttribute(pool_kernel, cudaFuncAttributeMaxDynamicSharedMemorySize, smemA);
    cudaFuncSetAttribute(gemm_kernel, cudaFuncAttributeMaxDynamicSharedMemorySize, smemG);

    prep_w_kernel<<<dim3(D_DIM / 32, O_DIM / 32), 256>>>(proj_w);
    pool_kernel<<<N_ROWS, 256, smemA>>>(articles, counts_w, attn_w, attn_b);
    gemm_kernel<<<G_TILES, 256, smemG>>>(counts_w, proj_b, ln_w, ln_b, no_news, out);
}